// round 14
// baseline (speedup 1.0000x reference)
#include <cuda_runtime.h>
#include <cuda_bf16.h>
#include <cstdint>

// ---------------- problem constants ----------------
#define N0v 1000000
#define N1v 102400
#define N2v 10240
#define N3v 1024
#define E0v 1024000
#define E1v 102400
#define E2v 10240
#define DINv 128
#define DHv  256
#define DOUTv 40

// ---------------- device scratch ----------------
__device__ float g_h1[(long)N1v * DHv];
__device__ float g_h2[N2v * DHv];
__device__ __nv_bfloat16 g_Ahi[(long)N1v * 256];
__device__ __nv_bfloat16 g_W0[256 * 256];
__device__ __nv_bfloat16 g_W1[256 * 512];
// single zeroed blob: cnt0i | cnt1i | cnt2(float) | aggr2(float)
#define ZB_CNT0   0
#define ZB_CNT1   (N1v)
#define ZB_CNT2   (N1v + N2v)
#define ZB_AGGR2  (N1v + N2v + N3v)
#define ZB_TOTAL  (N1v + N2v + N3v + N3v * DHv)
__device__ int g_zeroblob[ZB_TOTAL];
// CSR scratch
__device__ int g_part[N1v];
__device__ int g_bsums[128];
__device__ int g_start0[N1v];
__device__ int g_start1[N2v];
__device__ int g_rank[E0v + E1v];
__device__ int g_csr0[E0v];
__device__ int g_csr1[E1v];

// ---------------- asm helpers ----------------
__device__ __forceinline__ uint32_t smem_u32(const void* p) {
    uint32_t a;
    asm("{ .reg .u64 t; cvta.to.shared.u64 t, %1; cvt.u32.u64 %0, t; }"
        : "=r"(a) : "l"(p));
    return a;
}
__device__ __forceinline__ void ldmatrix_x4(uint32_t& r0, uint32_t& r1,
                                            uint32_t& r2, uint32_t& r3,
                                            uint32_t addr) {
    asm volatile("ldmatrix.sync.aligned.m8n8.x4.shared.b16 {%0,%1,%2,%3}, [%4];"
                 : "=r"(r0), "=r"(r1), "=r"(r2), "=r"(r3) : "r"(addr));
}
__device__ __forceinline__ void mma_bf16(float& c0, float& c1, float& c2, float& c3,
                                         uint32_t a0, uint32_t a1, uint32_t a2,
                                         uint32_t a3, uint32_t b0, uint32_t b1) {
    asm volatile(
        "mma.sync.aligned.m16n8k16.row.col.f32.bf16.bf16.f32 "
        "{%0,%1,%2,%3},{%4,%5,%6,%7},{%8,%9},{%0,%1,%2,%3};"
        : "+f"(c0), "+f"(c1), "+f"(c2), "+f"(c3)
        : "r"(a0), "r"(a1), "r"(a2), "r"(a3), "r"(b0), "r"(b1));
}
__device__ __forceinline__ void cp16(uint32_t dst, const void* src) {
    asm volatile("cp.async.cg.shared.global [%0], [%1], 16;"
                 :: "r"(dst), "l"(src));
}
#define CP_COMMIT() asm volatile("cp.async.commit_group;")
#define CP_WAIT0()  asm volatile("cp.async.wait_group 0;")
#define CP_WAIT1()  asm volatile("cp.async.wait_group 1;")

__device__ __forceinline__ void red_add_v4(float* p, float4 v) {
    asm volatile("red.global.add.v4.f32 [%0], {%1, %2, %3, %4};"
                 :: "l"(p), "f"(v.x), "f"(v.y), "f"(v.z), "f"(v.w) : "memory");
}

// ---------------- fused prep: hist0 | hist1 | convert_W --------------------
// blocks [0,4000): hist0; [4000,4400): hist1; [4400,5168): convert_W
__global__ void prep_kernel(const int* __restrict__ dst0,
                            const int* __restrict__ dst1,
                            const float* __restrict__ Wl0,
                            const float* __restrict__ Wr0,
                            const float* __restrict__ Wl1,
                            const float* __restrict__ Wr1,
                            int* __restrict__ cnt0,
                            int* __restrict__ cnt1,
                            int* __restrict__ rank,
                            __nv_bfloat16* __restrict__ W0,
                            __nv_bfloat16* __restrict__ W1) {
    int b = blockIdx.x;
    int tid = threadIdx.x;
    if (b < E0v / 256) {
        int i = b * 256 + tid;
        rank[i] = atomicAdd(&cnt0[__ldg(&dst0[i])], 1);
    } else if (b < E0v / 256 + E1v / 256) {
        int i = (b - E0v / 256) * 256 + tid;
        rank[E0v + i] = atomicAdd(&cnt1[__ldg(&dst1[i])], 1);
    } else {
        int idx = (b - (E0v / 256 + E1v / 256)) * 256 + tid;
        if (idx < 256 * 256) {
            int n = idx % 256, k2 = idx / 256;
            float w = (k2 < 128) ? __ldg(&Wl0[(long)k2 * 256 + n])
                                 : __ldg(&Wr0[(long)(k2 - 128) * 256 + n]);
            W0[(long)n * 256 + k2] = __float2bfloat16(w);
        } else {
            int j = idx - 256 * 256;
            int n = j % 256, k2 = j / 256;
            float w = (k2 < 256) ? __ldg(&Wl1[(long)k2 * 256 + n])
                                 : __ldg(&Wr1[(long)(k2 - 256) * 256 + n]);
            W1[(long)n * 512 + k2] = __float2bfloat16(w);
        }
    }
}

// ---------------- scan stage A (L0, 100 CTAs) ------------------------------
__global__ void scan_a_kernel(const int* __restrict__ cnt,
                              int* __restrict__ part,
                              int* __restrict__ bsums) {
    __shared__ int sh[1024];
    int tid = threadIdx.x;
    int i = blockIdx.x * 1024 + tid;
    sh[tid] = cnt[i];
    __syncthreads();
#pragma unroll
    for (int d = 1; d < 1024; d <<= 1) {
        int t = (tid >= d) ? sh[tid - d] : 0;
        __syncthreads();
        sh[tid] += t;
        __syncthreads();
    }
    part[i] = sh[tid];
    if (tid == 1023) bsums[blockIdx.x] = sh[tid];
}

// ---------------- scan stage B (blocks 0-99: L0 finish; block 100: L1 scan)
__global__ void scan_b_kernel(const int* __restrict__ part,
                              const int* __restrict__ bsums,
                              const int* __restrict__ cnt0,
                              int* __restrict__ start0,
                              const int* __restrict__ cnt1,
                              int* __restrict__ start1) {
    int tid = threadIdx.x;
    if (blockIdx.x < 100) {
        __shared__ int off;
        if (tid == 0) {
            int s = 0;
            for (int b = 0; b < (int)blockIdx.x; ++b) s += bsums[b];
            off = s;
        }
        __syncthreads();
        int i = blockIdx.x * 1024 + tid;
        start0[i] = part[i] + off - cnt0[i];
    } else {
        // single-CTA scan over cnt1[N2v], 10 elems/thread
        __shared__ int wsum[32];
        int lane = tid & 31, wid = tid >> 5;
        int base = tid * 10;
        int local[10];
        int s = 0;
#pragma unroll
        for (int i = 0; i < 10; ++i) { local[i] = cnt1[base + i]; s += local[i]; }
        int v = s;
#pragma unroll
        for (int d = 1; d < 32; d <<= 1) {
            int t = __shfl_up_sync(0xffffffffu, v, d);
            if (lane >= d) v += t;
        }
        if (lane == 31) wsum[wid] = v;
        __syncthreads();
        if (wid == 0) {
            int w = wsum[lane];
#pragma unroll
            for (int d = 1; d < 32; d <<= 1) {
                int t = __shfl_up_sync(0xffffffffu, w, d);
                if (lane >= d) w += t;
            }
            wsum[lane] = w;
        }
        __syncthreads();
        int running = v - s + (wid ? wsum[wid - 1] : 0);
#pragma unroll
        for (int i = 0; i < 10; ++i) {
            start1[base + i] = running;
            running += local[i];
        }
    }
}

// ---------------- fused scatter (L0 + L1) ----------------------------------
__global__ void scatter_kernel(const int* __restrict__ src0,
                               const int* __restrict__ dst0,
                               const int* __restrict__ src1,
                               const int* __restrict__ dst1,
                               const int* __restrict__ start0,
                               const int* __restrict__ start1,
                               const int* __restrict__ rank,
                               int* __restrict__ csr0,
                               int* __restrict__ csr1) {
    int i = blockIdx.x * blockDim.x + threadIdx.x;
    if (i < E0v) {
        int d = __ldg(&dst0[i]);
        csr0[__ldg(&start0[d]) + __ldg(&rank[i])] = __ldg(&src0[i]);
    } else {
        int j = i - E0v;
        int d = __ldg(&dst1[j]);
        csr1[__ldg(&start1[d]) + __ldg(&rank[E0v + j])] = __ldg(&src1[j]);
    }
}

// ---------------- bf16 helpers ----------------
__device__ __forceinline__ uint32_t pack_hi2(float x, float y) {
    __nv_bfloat162 hp{__float2bfloat16(x), __float2bfloat16(y)};
    return *reinterpret_cast<uint32_t*>(&hp);
}

// ---------------- gather-mean + target convert (generic) -------------------
template <int V4>
__global__ void gather_mean_kernel(const float* __restrict__ H,
                                   const int* __restrict__ csr,
                                   const int* __restrict__ start,
                                   const int* __restrict__ cnt,
                                   __nv_bfloat16* __restrict__ A) {
    constexpr int J = V4 / 32;
    constexpr int K2 = V4 * 8;
    int w = blockIdx.x * 8 + (threadIdx.x >> 5);
    int lane = threadIdx.x & 31;
    int beg = __ldg(&start[w]);
    int c = __ldg(&cnt[w]);
    const float4* x4 = reinterpret_cast<const float4*>(H);

    float4 acc[J];
#pragma unroll
    for (int j = 0; j < J; ++j) acc[j] = make_float4(0.f, 0.f, 0.f, 0.f);

    int e = 0;
    for (; e + 4 <= c; e += 4) {
        int s0 = __ldg(&csr[beg + e]);
        int s1 = __ldg(&csr[beg + e + 1]);
        int s2 = __ldg(&csr[beg + e + 2]);
        int s3 = __ldg(&csr[beg + e + 3]);
#pragma unroll
        for (int j = 0; j < J; ++j) {
            float4 v0 = __ldcs(&x4[(long)s0 * V4 + lane + j * 32]);
            float4 v1 = __ldcs(&x4[(long)s1 * V4 + lane + j * 32]);
            float4 v2 = __ldcs(&x4[(long)s2 * V4 + lane + j * 32]);
            float4 v3 = __ldcs(&x4[(long)s3 * V4 + lane + j * 32]);
            acc[j].x += v0.x + v1.x + v2.x + v3.x;
            acc[j].y += v0.y + v1.y + v2.y + v3.y;
            acc[j].z += v0.z + v1.z + v2.z + v3.z;
            acc[j].w += v0.w + v1.w + v2.w + v3.w;
        }
    }
    for (; e < c; ++e) {
        int s0 = __ldg(&csr[beg + e]);
#pragma unroll
        for (int j = 0; j < J; ++j) {
            float4 v0 = __ldcs(&x4[(long)s0 * V4 + lane + j * 32]);
            acc[j].x += v0.x; acc[j].y += v0.y;
            acc[j].z += v0.z; acc[j].w += v0.w;
        }
    }
    float inv = 1.0f / fmaxf((float)c, 1.0f);
#pragma unroll
    for (int j = 0; j < J; ++j) {
        long o = (long)w * K2 + (lane + j * 32) * 4;
        *(uint2*)(A + o) = make_uint2(
            pack_hi2(acc[j].x * inv, acc[j].y * inv),
            pack_hi2(acc[j].z * inv, acc[j].w * inv));
    }
#pragma unroll
    for (int j = 0; j < J; ++j) {
        float4 t = __ldg(&x4[(long)w * V4 + lane + j * 32]);
        long o = (long)w * K2 + V4 * 4 + (lane + j * 32) * 4;
        *(uint2*)(A + o) = make_uint2(pack_hi2(t.x, t.y), pack_hi2(t.z, t.w));
    }
}

// ---------------- edge aggregation (layer 2): red.v4 path ------------------
template <int V4, int EPW>
__global__ void edge_agg_kernel(const float* __restrict__ H,
                                const int* __restrict__ src,
                                const int* __restrict__ dst,
                                float* __restrict__ aggr,
                                float* __restrict__ cnt, int E) {
    constexpr int J = V4 / 32;
    int w = (blockIdx.x * blockDim.x + threadIdx.x) >> 5;
    int lane = threadIdx.x & 31;
    long e0 = (long)w * EPW;
    if (e0 >= E) return;

    int sv = 0, dv = 0;
    if (lane < EPW) {
        sv = __ldg(&src[e0 + lane]);
        dv = __ldg(&dst[e0 + lane]);
    }
    float4 vals[EPW][J];
    int dIdx[EPW];
#pragma unroll
    for (int i = 0; i < EPW; ++i) {
        int s = __shfl_sync(0xffffffffu, sv, i);
        dIdx[i] = __shfl_sync(0xffffffffu, dv, i);
        const float4* sp = reinterpret_cast<const float4*>(H) + (long)s * V4;
#pragma unroll
        for (int j = 0; j < J; ++j)
            vals[i][j] = __ldcs(&sp[lane + j * 32]);
    }
#pragma unroll
    for (int i = 0; i < EPW; ++i) {
        float* dp = aggr + (long)dIdx[i] * (V4 * 4);
#pragma unroll
        for (int j = 0; j < J; ++j)
            red_add_v4(dp + (lane + j * 32) * 4, vals[i][j]);
    }
    if (lane < EPW) atomicAdd(cnt + dv, 1.0f);
}

// ---------------- 1-term bf16 GEMM: C = act(A @ W^T + bias) ----------------
template <int K2>
__global__ __launch_bounds__(256, 2)
void mma_gemm2_kernel(const __nv_bfloat16* __restrict__ Ahi,
                      const __nv_bfloat16* __restrict__ W,
                      const float* __restrict__ bias,
                      float* __restrict__ C,
                      int Ntot, int relu) {
    constexpr int NT = K2 / 32;
    constexpr uint32_t STG = 20480u;
    extern __shared__ __align__(16) __nv_bfloat16 sm[];
    const uint32_t smBase = smem_u32(sm);

    const int tid = threadIdx.x;
    const int lane = tid & 31;
    const int wid = tid >> 5;
    const int warpR = wid & 1;
    const int warpC = wid >> 1;
    const int rowBase = blockIdx.y * 128;
    const int colBase = blockIdx.x * 128;

    const int cpRow = tid >> 1;
    const int cpOff = (tid & 1) * 32;

    const int aRow = warpR * 64 + (lane & 15);
    const int aCol = (lane >> 4) * 8;
    const int bRow = warpC * 32 + (lane & 7) + ((lane >> 4) << 3);
    const int bCol = ((lane >> 3) & 1) * 8;
    const uint32_t aAddr0 = smBase + (uint32_t)aRow * 80 + (uint32_t)aCol * 2;
    const uint32_t bAddr0 = smBase + 10240u + (uint32_t)bRow * 80 + (uint32_t)bCol * 2;

    float acc[4][4][4];
#pragma unroll
    for (int i = 0; i < 4; ++i)
#pragma unroll
        for (int j = 0; j < 4; ++j)
#pragma unroll
            for (int v = 0; v < 4; ++v) acc[i][j][v] = 0.f;

    auto issue = [&](int s, int kt) {
        const uint32_t base = smBase + (uint32_t)s * STG;
        const __nv_bfloat16* a = Ahi + (long)(rowBase + cpRow) * K2 + kt * 32;
        uint32_t dA = base + (uint32_t)cpRow * 80 + cpOff;
        cp16(dA, (const char*)a + cpOff);
        cp16(dA + 16, (const char*)a + cpOff + 16);
        const __nv_bfloat16* b = W + (long)(colBase + cpRow) * K2 + kt * 32;
        uint32_t dB = base + 10240u + (uint32_t)cpRow * 80 + cpOff;
        cp16(dB, (const char*)b + cpOff);
        cp16(dB + 16, (const char*)b + cpOff + 16);
    };

    issue(0, 0);
    CP_COMMIT();

    for (int kt = 0; kt < NT; ++kt) {
        const int s = kt & 1;
        if (kt + 1 < NT) {
            issue(s ^ 1, kt + 1);
            CP_COMMIT();
            CP_WAIT1();
        } else {
            CP_WAIT0();
        }
        __syncthreads();

        const uint32_t stA = aAddr0 + (uint32_t)s * STG;
        const uint32_t stB = bAddr0 + (uint32_t)s * STG;
#pragma unroll
        for (int ks = 0; ks < 2; ++ks) {
            const uint32_t ksOff = (uint32_t)ks * 32;
            uint32_t bh[4][2];
#pragma unroll
            for (int nfp = 0; nfp < 2; ++nfp) {
                uint32_t bd = stB + (uint32_t)nfp * 1280 + ksOff;
                ldmatrix_x4(bh[nfp * 2][0], bh[nfp * 2][1],
                            bh[nfp * 2 + 1][0], bh[nfp * 2 + 1][1], bd);
            }
#pragma unroll
            for (int mf = 0; mf < 4; ++mf) {
                uint32_t ah[4];
                uint32_t ad = stA + (uint32_t)mf * 1280 + ksOff;
                ldmatrix_x4(ah[0], ah[1], ah[2], ah[3], ad);
#pragma unroll
                for (int nf = 0; nf < 4; ++nf) {
                    float* c = acc[mf][nf];
                    mma_bf16(c[0], c[1], c[2], c[3],
                             ah[0], ah[1], ah[2], ah[3], bh[nf][0], bh[nf][1]);
                }
            }
        }
        __syncthreads();
    }

    const int gr = lane >> 2;
    const int gc = (lane & 3) * 2;
#pragma unroll
    for (int mf = 0; mf < 4; ++mf) {
#pragma unroll
        for (int nf = 0; nf < 4; ++nf) {
            int col = colBase + warpC * 32 + nf * 8 + gc;
            float b0 = bias[col], b1 = bias[col + 1];
            int row0 = rowBase + warpR * 64 + mf * 16 + gr;
            float* c = acc[mf][nf];
            float2 o0 = make_float2(c[0] + b0, c[1] + b1);
            float2 o1 = make_float2(c[2] + b0, c[3] + b1);
            if (relu) {
                o0.x = fmaxf(o0.x, 0.f); o0.y = fmaxf(o0.y, 0.f);
                o1.x = fmaxf(o1.x, 0.f); o1.y = fmaxf(o1.y, 0.f);
            }
            *(float2*)(C + (long)row0 * Ntot + col) = o0;
            *(float2*)(C + (long)(row0 + 8) * Ntot + col) = o1;
        }
    }
}

// ---------------- layer 2: dual GEMV + log_softmax ----------------
__global__ void layer2_kernel(const float* __restrict__ aggr2,
                              const float* __restrict__ cnt2,
                              const float* __restrict__ h2,
                              const float* __restrict__ Wl2,
                              const float* __restrict__ Wr2,
                              const float* __restrict__ b2,
                              float* __restrict__ out) {
    __shared__ float a[2 * DHv];
    __shared__ float c[DOUTv];
    __shared__ float lse;

    int row = blockIdx.x;
    int tid = threadIdx.x;
    float invc = 1.0f / fmaxf(cnt2[row], 1.0f);
    a[tid] = aggr2[(long)row * DHv + tid] * invc;
    a[DHv + tid] = h2[(long)row * DHv + tid];
    __syncthreads();

    if (tid < DOUTv) {
        float s = b2[tid];
#pragma unroll 8
        for (int k = 0; k < DHv; ++k)
            s = fmaf(a[k], __ldg(&Wl2[k * DOUTv + tid]), s);
#pragma unroll 8
        for (int k = 0; k < DHv; ++k)
            s = fmaf(a[DHv + k], __ldg(&Wr2[k * DOUTv + tid]), s);
        c[tid] = s;
    }
    __syncthreads();

    if (tid == 0) {
        float m = c[0];
#pragma unroll
        for (int j = 1; j < DOUTv; ++j) m = fmaxf(m, c[j]);
        float sum = 0.f;
#pragma unroll
        for (int j = 0; j < DOUTv; ++j) sum += expf(c[j] - m);
        lse = m + logf(sum);
    }
    __syncthreads();

    if (tid < DOUTv) out[(long)row * DOUTv + tid] = c[tid] - lse;
}

// ---------------- host launcher ----------------
extern "C" void kernel_launch(void* const* d_in, const int* in_sizes, int n_in,
                              void* d_out, int out_size) {
    const float* x   = (const float*)d_in[0];
    const int* src0  = (const int*)d_in[1];
    const int* dst0  = (const int*)d_in[2];
    const int* src1  = (const int*)d_in[3];
    const int* dst1  = (const int*)d_in[4];
    const int* src2  = (const int*)d_in[5];
    const int* dst2  = (const int*)d_in[6];
    const float* Wl0 = (const float*)d_in[7];
    const float* bl0 = (const float*)d_in[8];
    const float* Wr0 = (const float*)d_in[9];
    const float* Wl1 = (const float*)d_in[10];
    const float* bl1 = (const float*)d_in[11];
    const float* Wr1 = (const float*)d_in[12];
    const float* Wl2 = (const float*)d_in[13];
    const float* bl2 = (const float*)d_in[14];
    const float* Wr2 = (const float*)d_in[15];
    float* out = (float*)d_out;

    float *h1, *h2;
    __nv_bfloat16 *Ahi, *W0, *W1;
    int *zb, *part, *bsums, *start0, *start1, *rankp, *csr0, *csr1;
    cudaGetSymbolAddress((void**)&h1,    g_h1);
    cudaGetSymbolAddress((void**)&h2,    g_h2);
    cudaGetSymbolAddress((void**)&Ahi,   g_Ahi);
    cudaGetSymbolAddress((void**)&W0,    g_W0);
    cudaGetSymbolAddress((void**)&W1,    g_W1);
    cudaGetSymbolAddress((void**)&zb,    g_zeroblob);
    cudaGetSymbolAddress((void**)&part,  g_part);
    cudaGetSymbolAddress((void**)&bsums, g_bsums);
    cudaGetSymbolAddress((void**)&start0,g_start0);
    cudaGetSymbolAddress((void**)&start1,g_start1);
    cudaGetSymbolAddress((void**)&rankp, g_rank);
    cudaGetSymbolAddress((void**)&csr0,  g_csr0);
    cudaGetSymbolAddress((void**)&csr1,  g_csr1);

    int* cnt0i   = zb + ZB_CNT0;
    int* cnt1i   = zb + ZB_CNT1;
    float* cnt2  = (float*)(zb + ZB_CNT2);
    float* aggr2 = (float*)(zb + ZB_AGGR2);

    const int smemG = 40960;
    cudaFuncSetAttribute(mma_gemm2_kernel<256>,
                         cudaFuncAttributeMaxDynamicSharedMemorySize, smemG);
    cudaFuncSetAttribute(mma_gemm2_kernel<512>,
                         cudaFuncAttributeMaxDynamicSharedMemorySize, smemG);

    // 1. single zero-fill memset node
    cudaMemsetAsync(zb, 0, ZB_TOTAL * sizeof(int), 0);

    // 2. fused prep: hist0 + hist1 + convert_W
    const int prepBlocks = E0v / 256 + E1v / 256 + (256 * 256 + 256 * 512) / 256;
    prep_kernel<<<prepBlocks, 256>>>(dst0, dst1, Wl0, Wr0, Wl1, Wr1,
                                     cnt0i, cnt1i, rankp, W0, W1);

    // 3-4. scans (L0 two-pass; L1 folded into scan_b block 100)
    scan_a_kernel<<<N1v / 1024, 1024>>>(cnt0i, part, bsums);
    scan_b_kernel<<<101, 1024>>>(part, bsums, cnt0i, start0, cnt1i, start1);

    // 5. fused scatter (L0 + L1)
    scatter_kernel<<<(E0v + E1v) / 256, 256>>>(src0, dst0, src1, dst1,
                                               start0, start1, rankp,
                                               csr0, csr1);

    // 6-7. layer 0
    gather_mean_kernel<32><<<N1v / 8, 256>>>(x, csr0, start0, cnt0i, Ahi);
    mma_gemm2_kernel<256><<<dim3(2, N1v / 128), 256, smemG>>>(
        Ahi, W0, bl0, h1, DHv, 1);

    // 8-9. layer 1
    gather_mean_kernel<64><<<N2v / 8, 256>>>(h1, csr1, start1, cnt1i, Ahi);
    mma_gemm2_kernel<512><<<dim3(2, N2v / 128), 256, smemG>>>(
        Ahi, W1, bl1, h2, DHv, 1);

    // 10-11. layer 2 + log_softmax
    edge_agg_kernel<64, 4><<<E2v / 4 / 8, 256>>>(h2, src2, dst2, aggr2, cnt2, E2v);
    layer2_kernel<<<N3v, 256>>>(aggr2, cnt2, h2, Wl2, Wr2, bl2, out);

    (void)in_sizes; (void)n_in; (void)out_size;
}

// round 15
// speedup vs baseline: 1.2031x; 1.2031x over previous
#include <cuda_runtime.h>
#include <cuda_bf16.h>
#include <cstdint>

// ---------------- problem constants ----------------
#define N0v 1000000
#define N1v 102400
#define N2v 10240
#define N3v 1024
#define E0v 1024000
#define E1v 102400
#define E2v 10240
#define DINv 128
#define DHv  256
#define DOUTv 40

// ---------------- device scratch ----------------
__device__ float g_h1[(long)N1v * DHv];
__device__ float g_aggr2[N3v * DHv];
__device__ float g_cnt2[N3v];
__device__ float g_h2[N2v * DHv];
__device__ __nv_bfloat16 g_Ahi[(long)N1v * 256];
__device__ __nv_bfloat16 g_W0[256 * 256];
__device__ __nv_bfloat16 g_W1[256 * 512];
// CSR scratch
__device__ int g_cnt0i[N1v];
__device__ int g_part[N1v];
__device__ int g_bsums[128];
__device__ int g_start0[N1v];
__device__ int g_cnt1i[N2v];
__device__ int g_start1[N2v];
__device__ int g_rank[E0v];
__device__ int g_csr[E0v];

// ---------------- asm helpers ----------------
__device__ __forceinline__ uint32_t smem_u32(const void* p) {
    uint32_t a;
    asm("{ .reg .u64 t; cvta.to.shared.u64 t, %1; cvt.u32.u64 %0, t; }"
        : "=r"(a) : "l"(p));
    return a;
}
__device__ __forceinline__ void ldmatrix_x4(uint32_t& r0, uint32_t& r1,
                                            uint32_t& r2, uint32_t& r3,
                                            uint32_t addr) {
    asm volatile("ldmatrix.sync.aligned.m8n8.x4.shared.b16 {%0,%1,%2,%3}, [%4];"
                 : "=r"(r0), "=r"(r1), "=r"(r2), "=r"(r3) : "r"(addr));
}
__device__ __forceinline__ void mma_bf16(float& c0, float& c1, float& c2, float& c3,
                                         uint32_t a0, uint32_t a1, uint32_t a2,
                                         uint32_t a3, uint32_t b0, uint32_t b1) {
    asm volatile(
        "mma.sync.aligned.m16n8k16.row.col.f32.bf16.bf16.f32 "
        "{%0,%1,%2,%3},{%4,%5,%6,%7},{%8,%9},{%0,%1,%2,%3};"
        : "+f"(c0), "+f"(c1), "+f"(c2), "+f"(c3)
        : "r"(a0), "r"(a1), "r"(a2), "r"(a3), "r"(b0), "r"(b1));
}
__device__ __forceinline__ void cp16(uint32_t dst, const void* src) {
    asm volatile("cp.async.cg.shared.global [%0], [%1], 16;"
                 :: "r"(dst), "l"(src));
}
#define CP_COMMIT() asm volatile("cp.async.commit_group;")
#define CP_WAIT0()  asm volatile("cp.async.wait_group 0;")
#define CP_WAIT1()  asm volatile("cp.async.wait_group 1;")

__device__ __forceinline__ void red_add_v4(float* p, float4 v) {
    asm volatile("red.global.add.v4.f32 [%0], {%1, %2, %3, %4};"
                 :: "l"(p), "f"(v.x), "f"(v.y), "f"(v.z), "f"(v.w) : "memory");
}

// ---------------- CSR build: hist(x4 ILP) -> scan -> scatter(x4 ILP) -------
__global__ void hist_kernel(const int* __restrict__ dst, int* __restrict__ cnt,
                            int* __restrict__ rank, int E) {
    int i0 = (blockIdx.x * blockDim.x + threadIdx.x) * 4;
    if (i0 + 3 < E) {
        int d0 = __ldg(&dst[i0]);
        int d1 = __ldg(&dst[i0 + 1]);
        int d2 = __ldg(&dst[i0 + 2]);
        int d3 = __ldg(&dst[i0 + 3]);
        rank[i0]     = atomicAdd(&cnt[d0], 1);
        rank[i0 + 1] = atomicAdd(&cnt[d1], 1);
        rank[i0 + 2] = atomicAdd(&cnt[d2], 1);
        rank[i0 + 3] = atomicAdd(&cnt[d3], 1);
    }
}

__global__ void scan_a_kernel(const int* __restrict__ cnt,
                              int* __restrict__ part,
                              int* __restrict__ bsums) {
    __shared__ int sh[1024];
    int tid = threadIdx.x;
    int i = blockIdx.x * 1024 + tid;
    sh[tid] = cnt[i];
    __syncthreads();
#pragma unroll
    for (int d = 1; d < 1024; d <<= 1) {
        int t = (tid >= d) ? sh[tid - d] : 0;
        __syncthreads();
        sh[tid] += t;
        __syncthreads();
    }
    part[i] = sh[tid];
    if (tid == 1023) bsums[blockIdx.x] = sh[tid];
}

__global__ void scan_b_kernel(const int* __restrict__ part,
                              const int* __restrict__ bsums,
                              const int* __restrict__ cnt,
                              int* __restrict__ start) {
    __shared__ int bs[128];
    __shared__ int off;
    int tid = threadIdx.x;
    if (tid < 100) bs[tid] = __ldg(&bsums[tid]);
    __syncthreads();
    if (tid == 0) {
        int s = 0;
        for (int b = 0; b < (int)blockIdx.x; ++b) s += bs[b];
        off = s;
    }
    __syncthreads();
    int i = blockIdx.x * 1024 + tid;
    start[i] = part[i] + off - cnt[i];
}

// small single-CTA scan for N2v = 10240
__global__ void scan_small_kernel(const int* __restrict__ cnt,
                                  int* __restrict__ start, int n) {
    __shared__ int wsum[32];
    int tid = threadIdx.x;
    int lane = tid & 31, wid = tid >> 5;
    int per = n / 1024;                 // 10
    int base = tid * per;
    int local[16];
    int s = 0;
    for (int i = 0; i < per; ++i) { local[i] = cnt[base + i]; s += local[i]; }
    int v = s;
#pragma unroll
    for (int d = 1; d < 32; d <<= 1) {
        int t = __shfl_up_sync(0xffffffffu, v, d);
        if (lane >= d) v += t;
    }
    if (lane == 31) wsum[wid] = v;
    __syncthreads();
    if (wid == 0) {
        int w = wsum[lane];
#pragma unroll
        for (int d = 1; d < 32; d <<= 1) {
            int t = __shfl_up_sync(0xffffffffu, w, d);
            if (lane >= d) w += t;
        }
        wsum[lane] = w;
    }
    __syncthreads();
    int running = v - s + (wid ? wsum[wid - 1] : 0);
    for (int i = 0; i < per; ++i) {
        start[base + i] = running;
        running += local[i];
    }
}

__global__ void scatter_kernel(const int* __restrict__ src,
                               const int* __restrict__ dst,
                               const int* __restrict__ start,
                               const int* __restrict__ rank,
                               int* __restrict__ csr, int E) {
    int i0 = (blockIdx.x * blockDim.x + threadIdx.x) * 4;
    if (i0 + 3 < E) {
        int d0 = __ldg(&dst[i0]);
        int d1 = __ldg(&dst[i0 + 1]);
        int d2 = __ldg(&dst[i0 + 2]);
        int d3 = __ldg(&dst[i0 + 3]);
        int r0 = __ldg(&rank[i0]);
        int r1 = __ldg(&rank[i0 + 1]);
        int r2 = __ldg(&rank[i0 + 2]);
        int r3 = __ldg(&rank[i0 + 3]);
        int s0 = __ldg(&src[i0]);
        int s1 = __ldg(&src[i0 + 1]);
        int s2 = __ldg(&src[i0 + 2]);
        int s3 = __ldg(&src[i0 + 3]);
        int p0 = __ldg(&start[d0]);
        int p1 = __ldg(&start[d1]);
        int p2 = __ldg(&start[d2]);
        int p3 = __ldg(&start[d3]);
        csr[p0 + r0] = s0;
        csr[p1 + r1] = s1;
        csr[p2 + r2] = s2;
        csr[p3 + r3] = s3;
    }
}

// ---------------- bf16 helpers ----------------
__device__ __forceinline__ uint32_t pack_hi2(float x, float y) {
    __nv_bfloat162 hp{__float2bfloat16(x), __float2bfloat16(y)};
    return *reinterpret_cast<uint32_t*>(&hp);
}

// ---------------- gather-mean + target convert (generic over row width) ----
template <int V4>
__global__ void gather_mean_kernel(const float* __restrict__ H,
                                   const int* __restrict__ csr,
                                   const int* __restrict__ start,
                                   const int* __restrict__ cnt,
                                   __nv_bfloat16* __restrict__ A) {
    constexpr int J = V4 / 32;
    constexpr int K2 = V4 * 8;
    int w = blockIdx.x * 8 + (threadIdx.x >> 5);
    int lane = threadIdx.x & 31;
    int beg = __ldg(&start[w]);
    int c = __ldg(&cnt[w]);
    const float4* x4 = reinterpret_cast<const float4*>(H);

    float4 acc[J];
#pragma unroll
    for (int j = 0; j < J; ++j) acc[j] = make_float4(0.f, 0.f, 0.f, 0.f);

    int e = 0;
    for (; e + 4 <= c; e += 4) {
        int s0 = __ldg(&csr[beg + e]);
        int s1 = __ldg(&csr[beg + e + 1]);
        int s2 = __ldg(&csr[beg + e + 2]);
        int s3 = __ldg(&csr[beg + e + 3]);
#pragma unroll
        for (int j = 0; j < J; ++j) {
            float4 v0 = __ldcs(&x4[(long)s0 * V4 + lane + j * 32]);
            float4 v1 = __ldcs(&x4[(long)s1 * V4 + lane + j * 32]);
            float4 v2 = __ldcs(&x4[(long)s2 * V4 + lane + j * 32]);
            float4 v3 = __ldcs(&x4[(long)s3 * V4 + lane + j * 32]);
            acc[j].x += v0.x + v1.x + v2.x + v3.x;
            acc[j].y += v0.y + v1.y + v2.y + v3.y;
            acc[j].z += v0.z + v1.z + v2.z + v3.z;
            acc[j].w += v0.w + v1.w + v2.w + v3.w;
        }
    }
    for (; e < c; ++e) {
        int s0 = __ldg(&csr[beg + e]);
#pragma unroll
        for (int j = 0; j < J; ++j) {
            float4 v0 = __ldcs(&x4[(long)s0 * V4 + lane + j * 32]);
            acc[j].x += v0.x; acc[j].y += v0.y;
            acc[j].z += v0.z; acc[j].w += v0.w;
        }
    }
    float inv = 1.0f / fmaxf((float)c, 1.0f);
#pragma unroll
    for (int j = 0; j < J; ++j) {
        long o = (long)w * K2 + (lane + j * 32) * 4;
        *(uint2*)(A + o) = make_uint2(
            pack_hi2(acc[j].x * inv, acc[j].y * inv),
            pack_hi2(acc[j].z * inv, acc[j].w * inv));
    }
#pragma unroll
    for (int j = 0; j < J; ++j) {
        float4 t = __ldg(&x4[(long)w * V4 + lane + j * 32]);
        long o = (long)w * K2 + V4 * 4 + (lane + j * 32) * 4;
        *(uint2*)(A + o) = make_uint2(pack_hi2(t.x, t.y), pack_hi2(t.z, t.w));
    }
}

// ---------------- edge aggregation (layer 2 only): red.v4 path -------------
template <int V4, int EPW>
__global__ void edge_agg_kernel(const float* __restrict__ H,
                                const int* __restrict__ src,
                                const int* __restrict__ dst,
                                float* __restrict__ aggr,
                                float* __restrict__ cnt, int E) {
    constexpr int J = V4 / 32;
    int w = (blockIdx.x * blockDim.x + threadIdx.x) >> 5;
    int lane = threadIdx.x & 31;
    long e0 = (long)w * EPW;
    if (e0 >= E) return;

    int sv = 0, dv = 0;
    if (lane < EPW) {
        sv = __ldg(&src[e0 + lane]);
        dv = __ldg(&dst[e0 + lane]);
    }
    float4 vals[EPW][J];
    int dIdx[EPW];
#pragma unroll
    for (int i = 0; i < EPW; ++i) {
        int s = __shfl_sync(0xffffffffu, sv, i);
        dIdx[i] = __shfl_sync(0xffffffffu, dv, i);
        const float4* sp = reinterpret_cast<const float4*>(H) + (long)s * V4;
#pragma unroll
        for (int j = 0; j < J; ++j)
            vals[i][j] = __ldcs(&sp[lane + j * 32]);
    }
#pragma unroll
    for (int i = 0; i < EPW; ++i) {
        float* dp = aggr + (long)dIdx[i] * (V4 * 4);
#pragma unroll
        for (int j = 0; j < J; ++j)
            red_add_v4(dp + (lane + j * 32) * 4, vals[i][j]);
    }
    if (lane < EPW) atomicAdd(cnt + dv, 1.0f);
}

// ---------------- both weight matrices -> bf16, transposed -----------------
__global__ void convert_W_kernel(const float* __restrict__ Wl0,
                                 const float* __restrict__ Wr0,
                                 const float* __restrict__ Wl1,
                                 const float* __restrict__ Wr1,
                                 __nv_bfloat16* __restrict__ W0,
                                 __nv_bfloat16* __restrict__ W1) {
    int idx = blockIdx.x * blockDim.x + threadIdx.x;
    if (idx < 256 * 256) {
        int n = idx % 256, k2 = idx / 256;
        float w = (k2 < 128) ? __ldg(&Wl0[(long)k2 * 256 + n])
                             : __ldg(&Wr0[(long)(k2 - 128) * 256 + n]);
        W0[(long)n * 256 + k2] = __float2bfloat16(w);
    } else {
        int j = idx - 256 * 256;
        int n = j % 256, k2 = j / 256;
        float w = (k2 < 256) ? __ldg(&Wl1[(long)k2 * 256 + n])
                             : __ldg(&Wr1[(long)(k2 - 256) * 256 + n]);
        W1[(long)n * 512 + k2] = __float2bfloat16(w);
    }
}

// ---------------- 1-term bf16 GEMM: C = act(A @ W^T + bias) ----------------
template <int K2>
__global__ __launch_bounds__(256, 2)
void mma_gemm2_kernel(const __nv_bfloat16* __restrict__ Ahi,
                      const __nv_bfloat16* __restrict__ W,
                      const float* __restrict__ bias,
                      float* __restrict__ C,
                      int Ntot, int relu) {
    constexpr int NT = K2 / 32;
    constexpr uint32_t STG = 20480u;
    extern __shared__ __align__(16) __nv_bfloat16 sm[];
    const uint32_t smBase = smem_u32(sm);

    const int tid = threadIdx.x;
    const int lane = tid & 31;
    const int wid = tid >> 5;
    const int warpR = wid & 1;
    const int warpC = wid >> 1;
    const int rowBase = blockIdx.y * 128;
    const int colBase = blockIdx.x * 128;

    const int cpRow = tid >> 1;
    const int cpOff = (tid & 1) * 32;

    const int aRow = warpR * 64 + (lane & 15);
    const int aCol = (lane >> 4) * 8;
    const int bRow = warpC * 32 + (lane & 7) + ((lane >> 4) << 3);
    const int bCol = ((lane >> 3) & 1) * 8;
    const uint32_t aAddr0 = smBase + (uint32_t)aRow * 80 + (uint32_t)aCol * 2;
    const uint32_t bAddr0 = smBase + 10240u + (uint32_t)bRow * 80 + (uint32_t)bCol * 2;

    float acc[4][4][4];
#pragma unroll
    for (int i = 0; i < 4; ++i)
#pragma unroll
        for (int j = 0; j < 4; ++j)
#pragma unroll
            for (int v = 0; v < 4; ++v) acc[i][j][v] = 0.f;

    auto issue = [&](int s, int kt) {
        const uint32_t base = smBase + (uint32_t)s * STG;
        const __nv_bfloat16* a = Ahi + (long)(rowBase + cpRow) * K2 + kt * 32;
        uint32_t dA = base + (uint32_t)cpRow * 80 + cpOff;
        cp16(dA, (const char*)a + cpOff);
        cp16(dA + 16, (const char*)a + cpOff + 16);
        const __nv_bfloat16* b = W + (long)(colBase + cpRow) * K2 + kt * 32;
        uint32_t dB = base + 10240u + (uint32_t)cpRow * 80 + cpOff;
        cp16(dB, (const char*)b + cpOff);
        cp16(dB + 16, (const char*)b + cpOff + 16);
    };

    issue(0, 0);
    CP_COMMIT();

    for (int kt = 0; kt < NT; ++kt) {
        const int s = kt & 1;
        if (kt + 1 < NT) {
            issue(s ^ 1, kt + 1);
            CP_COMMIT();
            CP_WAIT1();
        } else {
            CP_WAIT0();
        }
        __syncthreads();

        const uint32_t stA = aAddr0 + (uint32_t)s * STG;
        const uint32_t stB = bAddr0 + (uint32_t)s * STG;
#pragma unroll
        for (int ks = 0; ks < 2; ++ks) {
            const uint32_t ksOff = (uint32_t)ks * 32;
            uint32_t bh[4][2];
#pragma unroll
            for (int nfp = 0; nfp < 2; ++nfp) {
                uint32_t bd = stB + (uint32_t)nfp * 1280 + ksOff;
                ldmatrix_x4(bh[nfp * 2][0], bh[nfp * 2][1],
                            bh[nfp * 2 + 1][0], bh[nfp * 2 + 1][1], bd);
            }
#pragma unroll
            for (int mf = 0; mf < 4; ++mf) {
                uint32_t ah[4];
                uint32_t ad = stA + (uint32_t)mf * 1280 + ksOff;
                ldmatrix_x4(ah[0], ah[1], ah[2], ah[3], ad);
#pragma unroll
                for (int nf = 0; nf < 4; ++nf) {
                    float* c = acc[mf][nf];
                    mma_bf16(c[0], c[1], c[2], c[3],
                             ah[0], ah[1], ah[2], ah[3], bh[nf][0], bh[nf][1]);
                }
            }
        }
        __syncthreads();
    }

    const int gr = lane >> 2;
    const int gc = (lane & 3) * 2;
#pragma unroll
    for (int mf = 0; mf < 4; ++mf) {
#pragma unroll
        for (int nf = 0; nf < 4; ++nf) {
            int col = colBase + warpC * 32 + nf * 8 + gc;
            float b0 = bias[col], b1 = bias[col + 1];
            int row0 = rowBase + warpR * 64 + mf * 16 + gr;
            float* c = acc[mf][nf];
            float2 o0 = make_float2(c[0] + b0, c[1] + b1);
            float2 o1 = make_float2(c[2] + b0, c[3] + b1);
            if (relu) {
                o0.x = fmaxf(o0.x, 0.f); o0.y = fmaxf(o0.y, 0.f);
                o1.x = fmaxf(o1.x, 0.f); o1.y = fmaxf(o1.y, 0.f);
            }
            *(float2*)(C + (long)row0 * Ntot + col) = o0;
            *(float2*)(C + (long)(row0 + 8) * Ntot + col) = o1;
        }
    }
}

// ---------------- layer 2: dual GEMV + log_softmax ----------------
__global__ void layer2_kernel(const float* __restrict__ aggr2,
                              const float* __restrict__ cnt2,
                              const float* __restrict__ h2,
                              const float* __restrict__ Wl2,
                              const float* __restrict__ Wr2,
                              const float* __restrict__ b2,
                              float* __restrict__ out) {
    __shared__ float a[2 * DHv];
    __shared__ float c[DOUTv];
    __shared__ float lse;

    int row = blockIdx.x;
    int tid = threadIdx.x;
    float invc = 1.0f / fmaxf(cnt2[row], 1.0f);
    a[tid] = aggr2[(long)row * DHv + tid] * invc;
    a[DHv + tid] = h2[(long)row * DHv + tid];
    __syncthreads();

    if (tid < DOUTv) {
        float s = b2[tid];
#pragma unroll 8
        for (int k = 0; k < DHv; ++k)
            s = fmaf(a[k], __ldg(&Wl2[k * DOUTv + tid]), s);
#pragma unroll 8
        for (int k = 0; k < DHv; ++k)
            s = fmaf(a[DHv + k], __ldg(&Wr2[k * DOUTv + tid]), s);
        c[tid] = s;
    }
    __syncthreads();

    if (tid == 0) {
        float m = c[0];
#pragma unroll
        for (int j = 1; j < DOUTv; ++j) m = fmaxf(m, c[j]);
        float sum = 0.f;
#pragma unroll
        for (int j = 0; j < DOUTv; ++j) sum += expf(c[j] - m);
        lse = m + logf(sum);
    }
    __syncthreads();

    if (tid < DOUTv) out[(long)row * DOUTv + tid] = c[tid] - lse;
}

// ---------------- host launcher ----------------
extern "C" void kernel_launch(void* const* d_in, const int* in_sizes, int n_in,
                              void* d_out, int out_size) {
    const float* x   = (const float*)d_in[0];
    const int* src0  = (const int*)d_in[1];
    const int* dst0  = (const int*)d_in[2];
    const int* src1  = (const int*)d_in[3];
    const int* dst1  = (const int*)d_in[4];
    const int* src2  = (const int*)d_in[5];
    const int* dst2  = (const int*)d_in[6];
    const float* Wl0 = (const float*)d_in[7];
    const float* bl0 = (const float*)d_in[8];
    const float* Wr0 = (const float*)d_in[9];
    const float* Wl1 = (const float*)d_in[10];
    const float* bl1 = (const float*)d_in[11];
    const float* Wr1 = (const float*)d_in[12];
    const float* Wl2 = (const float*)d_in[13];
    const float* bl2 = (const float*)d_in[14];
    const float* Wr2 = (const float*)d_in[15];
    float* out = (float*)d_out;

    float *h1, *h2, *aggr2, *cnt2;
    __nv_bfloat16 *Ahi, *W0, *W1;
    int *cnt0i, *part, *bsums, *start0, *cnt1i, *start1, *rankp, *csr;
    cudaGetSymbolAddress((void**)&h1,    g_h1);
    cudaGetSymbolAddress((void**)&h2,    g_h2);
    cudaGetSymbolAddress((void**)&aggr2, g_aggr2);
    cudaGetSymbolAddress((void**)&cnt2,  g_cnt2);
    cudaGetSymbolAddress((void**)&Ahi,   g_Ahi);
    cudaGetSymbolAddress((void**)&W0,    g_W0);
    cudaGetSymbolAddress((void**)&W1,    g_W1);
    cudaGetSymbolAddress((void**)&cnt0i, g_cnt0i);
    cudaGetSymbolAddress((void**)&part,  g_part);
    cudaGetSymbolAddress((void**)&bsums, g_bsums);
    cudaGetSymbolAddress((void**)&start0,g_start0);
    cudaGetSymbolAddress((void**)&cnt1i, g_cnt1i);
    cudaGetSymbolAddress((void**)&start1,g_start1);
    cudaGetSymbolAddress((void**)&rankp, g_rank);
    cudaGetSymbolAddress((void**)&csr,   g_csr);

    const int smemG = 40960;
    cudaFuncSetAttribute(mma_gemm2_kernel<256>,
                         cudaFuncAttributeMaxDynamicSharedMemorySize, smemG);
    cudaFuncSetAttribute(mma_gemm2_kernel<512>,
                         cudaFuncAttributeMaxDynamicSharedMemorySize, smemG);

    // ----- zero-fill via graph memset nodes -----
    cudaMemsetAsync(cnt0i, 0, N1v * sizeof(int), 0);
    cudaMemsetAsync(cnt1i, 0, N2v * sizeof(int), 0);
    cudaMemsetAsync(aggr2, 0, (long)N3v * DHv * sizeof(float), 0);
    cudaMemsetAsync(cnt2, 0, N3v * sizeof(float), 0);

    // ----- weights for both layers, up front -----
    convert_W_kernel<<<(256 * 256 + 256 * 512) / 256, 256>>>(
        Wl0, Wr0, Wl1, Wr1, W0, W1);

    // ----- layer 0 (CSR aggregation) -----
    hist_kernel<<<E0v / 4 / 256, 256>>>(dst0, cnt0i, rankp, E0v);
    scan_a_kernel<<<N1v / 1024, 1024>>>(cnt0i, part, bsums);
    scan_b_kernel<<<N1v / 1024, 1024>>>(part, bsums, cnt0i, start0);
    scatter_kernel<<<E0v / 4 / 256, 256>>>(src0, dst0, start0, rankp, csr, E0v);
    gather_mean_kernel<32><<<N1v / 8, 256>>>(x, csr, start0, cnt0i, Ahi);
    mma_gemm2_kernel<256><<<dim3(2, N1v / 128), 256, smemG>>>(
        Ahi, W0, bl0, h1, DHv, 1);

    // ----- layer 1 (CSR aggregation; rank/csr reused after L0 done) -----
    hist_kernel<<<E1v / 4 / 256, 256>>>(dst1, cnt1i, rankp, E1v);
    scan_small_kernel<<<1, 1024>>>(cnt1i, start1, N2v);
    scatter_kernel<<<E1v / 4 / 256, 256>>>(src1, dst1, start1, rankp, csr, E1v);
    gather_mean_kernel<64><<<N2v / 8, 256>>>(h1, csr, start1, cnt1i, Ahi);
    mma_gemm2_kernel<512><<<dim3(2, N2v / 128), 256, smemG>>>(
        Ahi, W1, bl1, h2, DHv, 1);

    // ----- layer 2 + log_softmax -----
    edge_agg_kernel<64, 4><<<E2v / 4 / 8, 256>>>(h2, src2, dst2, aggr2, cnt2, E2v);
    layer2_kernel<<<N3v, 256>>>(aggr2, cnt2, h2, Wl2, Wr2, bl2, out);

    (void)in_sizes; (void)n_in; (void)out_size;
}

// round 16
// speedup vs baseline: 1.2329x; 1.0248x over previous
#include <cuda_runtime.h>
#include <cuda_bf16.h>
#include <cstdint>

// ---------------- problem constants ----------------
#define N0v 1000000
#define N1v 102400
#define N2v 10240
#define N3v 1024
#define E0v 1024000
#define E1v 102400
#define E2v 10240
#define DINv 128
#define DHv  256
#define DOUTv 40

// ---------------- device scratch ----------------
__device__ float g_h1[(long)N1v * DHv];
__device__ float g_aggr2[N3v * DHv];
__device__ float g_cnt2[N3v];
__device__ float g_h2[N2v * DHv];
__device__ __nv_bfloat16 g_Ahi[(long)N1v * 256];
__device__ __nv_bfloat16 g_W0[256 * 256];
__device__ __nv_bfloat16 g_W1[256 * 512];
// CSR scratch
__device__ int g_cnt0i[N1v];
__device__ int g_part[N1v];
__device__ int g_bsums[128];
__device__ int g_start0[N1v];
__device__ int g_cnt1i[N2v];
__device__ int g_start1[N2v];
__device__ int g_rank0[E0v];
__device__ int g_rank1[E1v];
__device__ int g_csr0[E0v];
__device__ int g_csr1[E1v];

// ---------------- asm helpers ----------------
__device__ __forceinline__ uint32_t smem_u32(const void* p) {
    uint32_t a;
    asm("{ .reg .u64 t; cvta.to.shared.u64 t, %1; cvt.u32.u64 %0, t; }"
        : "=r"(a) : "l"(p));
    return a;
}
__device__ __forceinline__ void ldmatrix_x4(uint32_t& r0, uint32_t& r1,
                                            uint32_t& r2, uint32_t& r3,
                                            uint32_t addr) {
    asm volatile("ldmatrix.sync.aligned.m8n8.x4.shared.b16 {%0,%1,%2,%3}, [%4];"
                 : "=r"(r0), "=r"(r1), "=r"(r2), "=r"(r3) : "r"(addr));
}
__device__ __forceinline__ void mma_bf16(float& c0, float& c1, float& c2, float& c3,
                                         uint32_t a0, uint32_t a1, uint32_t a2,
                                         uint32_t a3, uint32_t b0, uint32_t b1) {
    asm volatile(
        "mma.sync.aligned.m16n8k16.row.col.f32.bf16.bf16.f32 "
        "{%0,%1,%2,%3},{%4,%5,%6,%7},{%8,%9},{%0,%1,%2,%3};"
        : "+f"(c0), "+f"(c1), "+f"(c2), "+f"(c3)
        : "r"(a0), "r"(a1), "r"(a2), "r"(a3), "r"(b0), "r"(b1));
}
__device__ __forceinline__ void cp16(uint32_t dst, const void* src) {
    asm volatile("cp.async.cg.shared.global [%0], [%1], 16;"
                 :: "r"(dst), "l"(src));
}
#define CP_COMMIT() asm volatile("cp.async.commit_group;")
#define CP_WAIT0()  asm volatile("cp.async.wait_group 0;")
#define CP_WAIT1()  asm volatile("cp.async.wait_group 1;")

__device__ __forceinline__ void red_add_v4(float* p, float4 v) {
    asm volatile("red.global.add.v4.f32 [%0], {%1, %2, %3, %4};"
                 :: "l"(p), "f"(v.x), "f"(v.y), "f"(v.z), "f"(v.w) : "memory");
}

// ---------------- CSR build: hist(x4 ILP) -> scan -> scatter(x4 ILP) -------
__global__ void hist_kernel(const int* __restrict__ dst, int* __restrict__ cnt,
                            int* __restrict__ rank, int E) {
    int i0 = (blockIdx.x * blockDim.x + threadIdx.x) * 4;
    if (i0 + 3 < E) {
        int d0 = __ldg(&dst[i0]);
        int d1 = __ldg(&dst[i0 + 1]);
        int d2 = __ldg(&dst[i0 + 2]);
        int d3 = __ldg(&dst[i0 + 3]);
        rank[i0]     = atomicAdd(&cnt[d0], 1);
        rank[i0 + 1] = atomicAdd(&cnt[d1], 1);
        rank[i0 + 2] = atomicAdd(&cnt[d2], 1);
        rank[i0 + 3] = atomicAdd(&cnt[d3], 1);
    }
}

__global__ void scan_a_kernel(const int* __restrict__ cnt,
                              int* __restrict__ part,
                              int* __restrict__ bsums) {
    __shared__ int sh[1024];
    int tid = threadIdx.x;
    int i = blockIdx.x * 1024 + tid;
    sh[tid] = cnt[i];
    __syncthreads();
#pragma unroll
    for (int d = 1; d < 1024; d <<= 1) {
        int t = (tid >= d) ? sh[tid - d] : 0;
        __syncthreads();
        sh[tid] += t;
        __syncthreads();
    }
    part[i] = sh[tid];
    if (tid == 1023) bsums[blockIdx.x] = sh[tid];
}

__global__ void scan_b_kernel(const int* __restrict__ part,
                              const int* __restrict__ bsums,
                              const int* __restrict__ cnt,
                              int* __restrict__ start) {
    __shared__ int bs[128];
    __shared__ int off;
    int tid = threadIdx.x;
    if (tid < 100) bs[tid] = __ldg(&bsums[tid]);
    __syncthreads();
    if (tid == 0) {
        int s = 0;
        for (int b = 0; b < (int)blockIdx.x; ++b) s += bs[b];
        off = s;
    }
    __syncthreads();
    int i = blockIdx.x * 1024 + tid;
    start[i] = part[i] + off - cnt[i];
}

// small single-CTA scan for N2v = 10240
__global__ void scan_small_kernel(const int* __restrict__ cnt,
                                  int* __restrict__ start, int n) {
    __shared__ int wsum[32];
    int tid = threadIdx.x;
    int lane = tid & 31, wid = tid >> 5;
    int per = n / 1024;                 // 10
    int base = tid * per;
    int local[16];
    int s = 0;
    for (int i = 0; i < per; ++i) { local[i] = cnt[base + i]; s += local[i]; }
    int v = s;
#pragma unroll
    for (int d = 1; d < 32; d <<= 1) {
        int t = __shfl_up_sync(0xffffffffu, v, d);
        if (lane >= d) v += t;
    }
    if (lane == 31) wsum[wid] = v;
    __syncthreads();
    if (wid == 0) {
        int w = wsum[lane];
#pragma unroll
        for (int d = 1; d < 32; d <<= 1) {
            int t = __shfl_up_sync(0xffffffffu, w, d);
            if (lane >= d) w += t;
        }
        wsum[lane] = w;
    }
    __syncthreads();
    int running = v - s + (wid ? wsum[wid - 1] : 0);
    for (int i = 0; i < per; ++i) {
        start[base + i] = running;
        running += local[i];
    }
}

__global__ void scatter_kernel(const int* __restrict__ src,
                               const int* __restrict__ dst,
                               const int* __restrict__ start,
                               const int* __restrict__ rank,
                               int* __restrict__ csr, int E) {
    int i0 = (blockIdx.x * blockDim.x + threadIdx.x) * 4;
    if (i0 + 3 < E) {
        int d0 = __ldg(&dst[i0]);
        int d1 = __ldg(&dst[i0 + 1]);
        int d2 = __ldg(&dst[i0 + 2]);
        int d3 = __ldg(&dst[i0 + 3]);
        int r0 = __ldg(&rank[i0]);
        int r1 = __ldg(&rank[i0 + 1]);
        int r2 = __ldg(&rank[i0 + 2]);
        int r3 = __ldg(&rank[i0 + 3]);
        int s0 = __ldg(&src[i0]);
        int s1 = __ldg(&src[i0 + 1]);
        int s2 = __ldg(&src[i0 + 2]);
        int s3 = __ldg(&src[i0 + 3]);
        int p0 = __ldg(&start[d0]);
        int p1 = __ldg(&start[d1]);
        int p2 = __ldg(&start[d2]);
        int p3 = __ldg(&start[d3]);
        csr[p0 + r0] = s0;
        csr[p1 + r1] = s1;
        csr[p2 + r2] = s2;
        csr[p3 + r3] = s3;
    }
}

// ---------------- bf16 helpers ----------------
__device__ __forceinline__ uint32_t pack_hi2(float x, float y) {
    __nv_bfloat162 hp{__float2bfloat16(x), __float2bfloat16(y)};
    return *reinterpret_cast<uint32_t*>(&hp);
}

// ---------------- gather-mean + target convert, V4=32, 8-edge MLP ----------
__global__ void gather_mean32_kernel(const float* __restrict__ H,
                                     const int* __restrict__ csr,
                                     const int* __restrict__ start,
                                     const int* __restrict__ cnt,
                                     __nv_bfloat16* __restrict__ A) {
    int w = blockIdx.x * 8 + (threadIdx.x >> 5);
    int lane = threadIdx.x & 31;
    int beg = __ldg(&start[w]);
    int c = __ldg(&cnt[w]);
    const float4* x4 = reinterpret_cast<const float4*>(H);

    float4 acc = make_float4(0.f, 0.f, 0.f, 0.f);
    int e = 0;
    for (; e + 8 <= c; e += 8) {
        int sI[8];
#pragma unroll
        for (int q = 0; q < 8; ++q) sI[q] = __ldg(&csr[beg + e + q]);
        float4 v[8];
#pragma unroll
        for (int q = 0; q < 8; ++q) v[q] = __ldcs(&x4[(long)sI[q] * 32 + lane]);
#pragma unroll
        for (int q = 0; q < 8; ++q) {
            acc.x += v[q].x; acc.y += v[q].y;
            acc.z += v[q].z; acc.w += v[q].w;
        }
    }
    for (; e + 4 <= c; e += 4) {
        int s0 = __ldg(&csr[beg + e]);
        int s1 = __ldg(&csr[beg + e + 1]);
        int s2 = __ldg(&csr[beg + e + 2]);
        int s3 = __ldg(&csr[beg + e + 3]);
        float4 v0 = __ldcs(&x4[(long)s0 * 32 + lane]);
        float4 v1 = __ldcs(&x4[(long)s1 * 32 + lane]);
        float4 v2 = __ldcs(&x4[(long)s2 * 32 + lane]);
        float4 v3 = __ldcs(&x4[(long)s3 * 32 + lane]);
        acc.x += v0.x + v1.x + v2.x + v3.x;
        acc.y += v0.y + v1.y + v2.y + v3.y;
        acc.z += v0.z + v1.z + v2.z + v3.z;
        acc.w += v0.w + v1.w + v2.w + v3.w;
    }
    for (; e < c; ++e) {
        int s0 = __ldg(&csr[beg + e]);
        float4 v0 = __ldcs(&x4[(long)s0 * 32 + lane]);
        acc.x += v0.x; acc.y += v0.y; acc.z += v0.z; acc.w += v0.w;
    }
    float inv = 1.0f / fmaxf((float)c, 1.0f);
    long o = (long)w * 256 + lane * 4;
    *(uint2*)(A + o) = make_uint2(pack_hi2(acc.x * inv, acc.y * inv),
                                  pack_hi2(acc.z * inv, acc.w * inv));
    float4 t = __ldg(&x4[(long)w * 32 + lane]);
    o = (long)w * 256 + 128 + lane * 4;
    *(uint2*)(A + o) = make_uint2(pack_hi2(t.x, t.y), pack_hi2(t.z, t.w));
}

// ---------------- gather-mean + target convert, V4=64 (4-edge, MLP 8) ------
__global__ void gather_mean64_kernel(const float* __restrict__ H,
                                     const int* __restrict__ csr,
                                     const int* __restrict__ start,
                                     const int* __restrict__ cnt,
                                     __nv_bfloat16* __restrict__ A) {
    constexpr int V4 = 64, J = 2, K2 = 512;
    int w = blockIdx.x * 8 + (threadIdx.x >> 5);
    int lane = threadIdx.x & 31;
    int beg = __ldg(&start[w]);
    int c = __ldg(&cnt[w]);
    const float4* x4 = reinterpret_cast<const float4*>(H);

    float4 acc[J];
#pragma unroll
    for (int j = 0; j < J; ++j) acc[j] = make_float4(0.f, 0.f, 0.f, 0.f);

    int e = 0;
    for (; e + 4 <= c; e += 4) {
        int s0 = __ldg(&csr[beg + e]);
        int s1 = __ldg(&csr[beg + e + 1]);
        int s2 = __ldg(&csr[beg + e + 2]);
        int s3 = __ldg(&csr[beg + e + 3]);
#pragma unroll
        for (int j = 0; j < J; ++j) {
            float4 v0 = __ldcs(&x4[(long)s0 * V4 + lane + j * 32]);
            float4 v1 = __ldcs(&x4[(long)s1 * V4 + lane + j * 32]);
            float4 v2 = __ldcs(&x4[(long)s2 * V4 + lane + j * 32]);
            float4 v3 = __ldcs(&x4[(long)s3 * V4 + lane + j * 32]);
            acc[j].x += v0.x + v1.x + v2.x + v3.x;
            acc[j].y += v0.y + v1.y + v2.y + v3.y;
            acc[j].z += v0.z + v1.z + v2.z + v3.z;
            acc[j].w += v0.w + v1.w + v2.w + v3.w;
        }
    }
    for (; e < c; ++e) {
        int s0 = __ldg(&csr[beg + e]);
#pragma unroll
        for (int j = 0; j < J; ++j) {
            float4 v0 = __ldcs(&x4[(long)s0 * V4 + lane + j * 32]);
            acc[j].x += v0.x; acc[j].y += v0.y;
            acc[j].z += v0.z; acc[j].w += v0.w;
        }
    }
    float inv = 1.0f / fmaxf((float)c, 1.0f);
#pragma unroll
    for (int j = 0; j < J; ++j) {
        long o = (long)w * K2 + (lane + j * 32) * 4;
        *(uint2*)(A + o) = make_uint2(
            pack_hi2(acc[j].x * inv, acc[j].y * inv),
            pack_hi2(acc[j].z * inv, acc[j].w * inv));
    }
#pragma unroll
    for (int j = 0; j < J; ++j) {
        float4 t = __ldg(&x4[(long)w * V4 + lane + j * 32]);
        long o = (long)w * K2 + V4 * 4 + (lane + j * 32) * 4;
        *(uint2*)(A + o) = make_uint2(pack_hi2(t.x, t.y), pack_hi2(t.z, t.w));
    }
}

// ---------------- edge aggregation (layer 2): red.v4 path ------------------
template <int V4, int EPW>
__global__ void edge_agg_kernel(const float* __restrict__ H,
                                const int* __restrict__ src,
                                const int* __restrict__ dst,
                                float* __restrict__ aggr,
                                float* __restrict__ cnt, int E) {
    constexpr int J = V4 / 32;
    int w = (blockIdx.x * blockDim.x + threadIdx.x) >> 5;
    int lane = threadIdx.x & 31;
    long e0 = (long)w * EPW;
    if (e0 >= E) return;

    int sv = 0, dv = 0;
    if (lane < EPW) {
        sv = __ldg(&src[e0 + lane]);
        dv = __ldg(&dst[e0 + lane]);
    }
    float4 vals[EPW][J];
    int dIdx[EPW];
#pragma unroll
    for (int i = 0; i < EPW; ++i) {
        int s = __shfl_sync(0xffffffffu, sv, i);
        dIdx[i] = __shfl_sync(0xffffffffu, dv, i);
        const float4* sp = reinterpret_cast<const float4*>(H) + (long)s * V4;
#pragma unroll
        for (int j = 0; j < J; ++j)
            vals[i][j] = __ldcs(&sp[lane + j * 32]);
    }
#pragma unroll
    for (int i = 0; i < EPW; ++i) {
        float* dp = aggr + (long)dIdx[i] * (V4 * 4);
#pragma unroll
        for (int j = 0; j < J; ++j)
            red_add_v4(dp + (lane + j * 32) * 4, vals[i][j]);
    }
    if (lane < EPW) atomicAdd(cnt + dv, 1.0f);
}

// ---------------- both weight matrices -> bf16, transposed -----------------
__global__ void convert_W_kernel(const float* __restrict__ Wl0,
                                 const float* __restrict__ Wr0,
                                 const float* __restrict__ Wl1,
                                 const float* __restrict__ Wr1,
                                 __nv_bfloat16* __restrict__ W0,
                                 __nv_bfloat16* __restrict__ W1) {
    int idx = blockIdx.x * blockDim.x + threadIdx.x;
    if (idx < 256 * 256) {
        int n = idx % 256, k2 = idx / 256;
        float w = (k2 < 128) ? __ldg(&Wl0[(long)k2 * 256 + n])
                             : __ldg(&Wr0[(long)(k2 - 128) * 256 + n]);
        W0[(long)n * 256 + k2] = __float2bfloat16(w);
    } else {
        int j = idx - 256 * 256;
        int n = j % 256, k2 = j / 256;
        float w = (k2 < 256) ? __ldg(&Wl1[(long)k2 * 256 + n])
                             : __ldg(&Wr1[(long)(k2 - 256) * 256 + n]);
        W1[(long)n * 512 + k2] = __float2bfloat16(w);
    }
}

// ---------------- 1-term bf16 GEMM: C = act(A @ W^T + bias) ----------------
template <int K2>
__global__ __launch_bounds__(256, 2)
void mma_gemm2_kernel(const __nv_bfloat16* __restrict__ Ahi,
                      const __nv_bfloat16* __restrict__ W,
                      const float* __restrict__ bias,
                      float* __restrict__ C,
                      int Ntot, int relu) {
    constexpr int NT = K2 / 32;
    constexpr uint32_t STG = 20480u;
    extern __shared__ __align__(16) __nv_bfloat16 sm[];
    const uint32_t smBase = smem_u32(sm);

    const int tid = threadIdx.x;
    const int lane = tid & 31;
    const int wid = tid >> 5;
    const int warpR = wid & 1;
    const int warpC = wid >> 1;
    const int rowBase = blockIdx.y * 128;
    const int colBase = blockIdx.x * 128;

    const int cpRow = tid >> 1;
    const int cpOff = (tid & 1) * 32;

    const int aRow = warpR * 64 + (lane & 15);
    const int aCol = (lane >> 4) * 8;
    const int bRow = warpC * 32 + (lane & 7) + ((lane >> 4) << 3);
    const int bCol = ((lane >> 3) & 1) * 8;
    const uint32_t aAddr0 = smBase + (uint32_t)aRow * 80 + (uint32_t)aCol * 2;
    const uint32_t bAddr0 = smBase + 10240u + (uint32_t)bRow * 80 + (uint32_t)bCol * 2;

    float acc[4][4][4];
#pragma unroll
    for (int i = 0; i < 4; ++i)
#pragma unroll
        for (int j = 0; j < 4; ++j)
#pragma unroll
            for (int v = 0; v < 4; ++v) acc[i][j][v] = 0.f;

    auto issue = [&](int s, int kt) {
        const uint32_t base = smBase + (uint32_t)s * STG;
        const __nv_bfloat16* a = Ahi + (long)(rowBase + cpRow) * K2 + kt * 32;
        uint32_t dA = base + (uint32_t)cpRow * 80 + cpOff;
        cp16(dA, (const char*)a + cpOff);
        cp16(dA + 16, (const char*)a + cpOff + 16);
        const __nv_bfloat16* b = W + (long)(colBase + cpRow) * K2 + kt * 32;
        uint32_t dB = base + 10240u + (uint32_t)cpRow * 80 + cpOff;
        cp16(dB, (const char*)b + cpOff);
        cp16(dB + 16, (const char*)b + cpOff + 16);
    };

    issue(0, 0);
    CP_COMMIT();

    for (int kt = 0; kt < NT; ++kt) {
        const int s = kt & 1;
        if (kt + 1 < NT) {
            issue(s ^ 1, kt + 1);
            CP_COMMIT();
            CP_WAIT1();
        } else {
            CP_WAIT0();
        }
        __syncthreads();

        const uint32_t stA = aAddr0 + (uint32_t)s * STG;
        const uint32_t stB = bAddr0 + (uint32_t)s * STG;
#pragma unroll
        for (int ks = 0; ks < 2; ++ks) {
            const uint32_t ksOff = (uint32_t)ks * 32;
            uint32_t bh[4][2];
#pragma unroll
            for (int nfp = 0; nfp < 2; ++nfp) {
                uint32_t bd = stB + (uint32_t)nfp * 1280 + ksOff;
                ldmatrix_x4(bh[nfp * 2][0], bh[nfp * 2][1],
                            bh[nfp * 2 + 1][0], bh[nfp * 2 + 1][1], bd);
            }
#pragma unroll
            for (int mf = 0; mf < 4; ++mf) {
                uint32_t ah[4];
                uint32_t ad = stA + (uint32_t)mf * 1280 + ksOff;
                ldmatrix_x4(ah[0], ah[1], ah[2], ah[3], ad);
#pragma unroll
                for (int nf = 0; nf < 4; ++nf) {
                    float* c = acc[mf][nf];
                    mma_bf16(c[0], c[1], c[2], c[3],
                             ah[0], ah[1], ah[2], ah[3], bh[nf][0], bh[nf][1]);
                }
            }
        }
        __syncthreads();
    }

    const int gr = lane >> 2;
    const int gc = (lane & 3) * 2;
#pragma unroll
    for (int mf = 0; mf < 4; ++mf) {
#pragma unroll
        for (int nf = 0; nf < 4; ++nf) {
            int col = colBase + warpC * 32 + nf * 8 + gc;
            float b0 = bias[col], b1 = bias[col + 1];
            int row0 = rowBase + warpR * 64 + mf * 16 + gr;
            float* c = acc[mf][nf];
            float2 o0 = make_float2(c[0] + b0, c[1] + b1);
            float2 o1 = make_float2(c[2] + b0, c[3] + b1);
            if (relu) {
                o0.x = fmaxf(o0.x, 0.f); o0.y = fmaxf(o0.y, 0.f);
                o1.x = fmaxf(o1.x, 0.f); o1.y = fmaxf(o1.y, 0.f);
            }
            *(float2*)(C + (long)row0 * Ntot + col) = o0;
            *(float2*)(C + (long)(row0 + 8) * Ntot + col) = o1;
        }
    }
}

// ---------------- layer 2: dual GEMV + log_softmax ----------------
__global__ void layer2_kernel(const float* __restrict__ aggr2,
                              const float* __restrict__ cnt2,
                              const float* __restrict__ h2,
                              const float* __restrict__ Wl2,
                              const float* __restrict__ Wr2,
                              const float* __restrict__ b2,
                              float* __restrict__ out) {
    __shared__ float a[2 * DHv];
    __shared__ float c[DOUTv];
    __shared__ float lse;

    int row = blockIdx.x;
    int tid = threadIdx.x;
    float invc = 1.0f / fmaxf(cnt2[row], 1.0f);
    a[tid] = aggr2[(long)row * DHv + tid] * invc;
    a[DHv + tid] = h2[(long)row * DHv + tid];
    __syncthreads();

    if (tid < DOUTv) {
        float s = b2[tid];
#pragma unroll 8
        for (int k = 0; k < DHv; ++k)
            s = fmaf(a[k], __ldg(&Wl2[k * DOUTv + tid]), s);
#pragma unroll 8
        for (int k = 0; k < DHv; ++k)
            s = fmaf(a[DHv + k], __ldg(&Wr2[k * DOUTv + tid]), s);
        c[tid] = s;
    }
    __syncthreads();

    if (tid == 0) {
        float m = c[0];
#pragma unroll
        for (int j = 1; j < DOUTv; ++j) m = fmaxf(m, c[j]);
        float sum = 0.f;
#pragma unroll
        for (int j = 0; j < DOUTv; ++j) sum += expf(c[j] - m);
        lse = m + logf(sum);
    }
    __syncthreads();

    if (tid < DOUTv) out[(long)row * DOUTv + tid] = c[tid] - lse;
}

// ---------------- host launcher ----------------
extern "C" void kernel_launch(void* const* d_in, const int* in_sizes, int n_in,
                              void* d_out, int out_size) {
    const float* x   = (const float*)d_in[0];
    const int* src0  = (const int*)d_in[1];
    const int* dst0  = (const int*)d_in[2];
    const int* src1  = (const int*)d_in[3];
    const int* dst1  = (const int*)d_in[4];
    const int* src2  = (const int*)d_in[5];
    const int* dst2  = (const int*)d_in[6];
    const float* Wl0 = (const float*)d_in[7];
    const float* bl0 = (const float*)d_in[8];
    const float* Wr0 = (const float*)d_in[9];
    const float* Wl1 = (const float*)d_in[10];
    const float* bl1 = (const float*)d_in[11];
    const float* Wr1 = (const float*)d_in[12];
    const float* Wl2 = (const float*)d_in[13];
    const float* bl2 = (const float*)d_in[14];
    const float* Wr2 = (const float*)d_in[15];
    float* out = (float*)d_out;

    float *h1, *h2, *aggr2, *cnt2;
    __nv_bfloat16 *Ahi, *W0, *W1;
    int *cnt0i, *part, *bsums, *start0, *cnt1i, *start1;
    int *rank0, *rank1, *csr0, *csr1;
    cudaGetSymbolAddress((void**)&h1,    g_h1);
    cudaGetSymbolAddress((void**)&h2,    g_h2);
    cudaGetSymbolAddress((void**)&aggr2, g_aggr2);
    cudaGetSymbolAddress((void**)&cnt2,  g_cnt2);
    cudaGetSymbolAddress((void**)&Ahi,   g_Ahi);
    cudaGetSymbolAddress((void**)&W0,    g_W0);
    cudaGetSymbolAddress((void**)&W1,    g_W1);
    cudaGetSymbolAddress((void**)&cnt0i, g_cnt0i);
    cudaGetSymbolAddress((void**)&part,  g_part);
    cudaGetSymbolAddress((void**)&bsums, g_bsums);
    cudaGetSymbolAddress((void**)&start0,g_start0);
    cudaGetSymbolAddress((void**)&cnt1i, g_cnt1i);
    cudaGetSymbolAddress((void**)&start1,g_start1);
    cudaGetSymbolAddress((void**)&rank0, g_rank0);
    cudaGetSymbolAddress((void**)&rank1, g_rank1);
    cudaGetSymbolAddress((void**)&csr0,  g_csr0);
    cudaGetSymbolAddress((void**)&csr1,  g_csr1);

    const int smemG = 40960;
    cudaFuncSetAttribute(mma_gemm2_kernel<256>,
                         cudaFuncAttributeMaxDynamicSharedMemorySize, smemG);
    cudaFuncSetAttribute(mma_gemm2_kernel<512>,
                         cudaFuncAttributeMaxDynamicSharedMemorySize, smemG);

    // side stream + events (host objects; created on the uncaptured first call)
    static cudaStream_t s1 = nullptr;
    static cudaEvent_t evFork = nullptr, evSide = nullptr;
    if (s1 == nullptr) {
        cudaStreamCreateWithFlags(&s1, cudaStreamNonBlocking);
        cudaEventCreateWithFlags(&evFork, cudaEventDisableTiming);
        cudaEventCreateWithFlags(&evSide, cudaEventDisableTiming);
    }

    // ----- zero-fill (graph memset nodes, main stream) -----
    cudaMemsetAsync(cnt0i, 0, N1v * sizeof(int), 0);
    cudaMemsetAsync(cnt1i, 0, N2v * sizeof(int), 0);
    cudaMemsetAsync(aggr2, 0, (long)N3v * DHv * sizeof(float), 0);
    cudaMemsetAsync(cnt2, 0, N3v * sizeof(float), 0);

    // ----- fork: side stream does conv_W + full L1 CSR build -----
    cudaEventRecord(evFork, 0);
    cudaStreamWaitEvent(s1, evFork, 0);
    convert_W_kernel<<<(256 * 256 + 256 * 512) / 256, 256, 0, s1>>>(
        Wl0, Wr0, Wl1, Wr1, W0, W1);
    hist_kernel<<<E1v / 4 / 256, 256, 0, s1>>>(dst1, cnt1i, rank1, E1v);
    scan_small_kernel<<<1, 1024, 0, s1>>>(cnt1i, start1, N2v);
    scatter_kernel<<<E1v / 4 / 256, 256, 0, s1>>>(src1, dst1, start1, rank1,
                                                  csr1, E1v);
    cudaEventRecord(evSide, s1);

    // ----- main stream: L0 CSR build + gather0 -----
    hist_kernel<<<E0v / 4 / 256, 256>>>(dst0, cnt0i, rank0, E0v);
    scan_a_kernel<<<N1v / 1024, 1024>>>(cnt0i, part, bsums);
    scan_b_kernel<<<N1v / 1024, 1024>>>(part, bsums, cnt0i, start0);
    scatter_kernel<<<E0v / 4 / 256, 256>>>(src0, dst0, start0, rank0, csr0, E0v);
    gather_mean32_kernel<<<N1v / 8, 256>>>(x, csr0, start0, cnt0i, Ahi);

    // join: gemm0 needs W0; gather1 later needs csr1
    cudaStreamWaitEvent(0, evSide, 0);
    mma_gemm2_kernel<256><<<dim3(2, N1v / 128), 256, smemG>>>(
        Ahi, W0, bl0, h1, DHv, 1);

    // ----- layer 1 -----
    gather_mean64_kernel<<<N2v / 8, 256>>>(h1, csr1, start1, cnt1i, Ahi);
    mma_gemm2_kernel<512><<<dim3(2, N2v / 128), 256, smemG>>>(
        Ahi, W1, bl1, h2, DHv, 1);

    // ----- layer 2 + log_softmax -----
    edge_agg_kernel<64, 4><<<E2v / 4 / 8, 256>>>(h2, src2, dst2, aggr2, cnt2, E2v);
    layer2_kernel<<<N3v, 256>>>(aggr2, cnt2, h2, Wl2, Wr2, bl2, out);

    (void)in_sizes; (void)n_in; (void)out_size;
}